// round 11
// baseline (speedup 1.0000x reference)
#include <cuda_runtime.h>
#include <cuda_bf16.h>
#include <math.h>
#include <stdint.h>

#define NPIX (16*96*16384)
#define GN_N 393216

// ---------------- scratch ----------------------------------------------------
__device__ uint32_t g_xpk[NPIX];        // packed split x
__device__ uint32_t g_Rpk[NPIX];        // packed split residual R
__device__ uint32_t g_Apk[NPIX];        // packed split attn-block output A
__device__ float g_buf1[NPIX];          // conv out fp32 / attn o0
__device__ float g_buf4[NPIX];          // attn o1
__device__ float g_qkv[3*NPIX];
__device__ float g_part0[16384];
__device__ float g_part1[1024];
__device__ float g_part2[16384];
__device__ float g_stats[3*64*2];
__device__ float g_film[16*192];
__device__ uint32_t g_w1hi[41472], g_w1lo[41472];
__device__ uint32_t g_w2hi[41472], g_w2lo[41472];
__device__ uint32_t g_pwhi[4608],  g_pwlo[4608];
__device__ uint32_t g_qfh[16*13824], g_qfl[16*13824];   // folded qkv weights
__device__ float    g_qb2[16*288];                      // folded qkv bias

// ---------------- helpers ----------------------------------------------------
__device__ __forceinline__ void mma16816(float* c, const uint32_t* a,
                                         const uint32_t* b) {
    asm volatile(
        "mma.sync.aligned.m16n8k16.row.col.f32.bf16.bf16.f32 "
        "{%0,%1,%2,%3}, {%4,%5,%6,%7}, {%8,%9}, {%0,%1,%2,%3};"
        : "+f"(c[0]), "+f"(c[1]), "+f"(c[2]), "+f"(c[3])
        : "r"(a[0]), "r"(a[1]), "r"(a[2]), "r"(a[3]), "r"(b[0]), "r"(b[1]));
}
__device__ __forceinline__ uint32_t prmt(uint32_t a, uint32_t b, uint32_t s) {
    uint32_t r;
    asm("prmt.b32 %0, %1, %2, %3;" : "=r"(r) : "r"(a), "r"(b), "r"(s));
    return r;
}
__device__ __forceinline__ uint32_t packsplit(float v) {
    __nv_bfloat16 hv = __float2bfloat16(v);
    __nv_bfloat16 lv = __float2bfloat16(v - __bfloat162float(hv));
    return (uint32_t)__bfloat16_as_ushort(hv)
         | ((uint32_t)__bfloat16_as_ushort(lv) << 16);
}
__device__ __forceinline__ float unpacksum(uint32_t u) {
    return __bfloat162float(__ushort_as_bfloat16((unsigned short)(u & 0xFFFFu)))
         + __bfloat162float(__ushort_as_bfloat16((unsigned short)(u >> 16)));
}

// ---------------- prep: conv/proj weight pack --------------------------------
__global__ __launch_bounds__(256) void prep_k(
    const float* __restrict__ wsrc, uint32_t* __restrict__ dh,
    uint32_t* __restrict__ dl, int n, int is33)
{
    int i = blockIdx.x*256 + threadIdx.x;
    if (i >= n) return;
    float v0, v1;
    if (is33) {
        int kk = i / 4608, r = i - kk*4608;
        int co = r / 48, k2 = r - co*48, ci = k2 << 1;
        v0 = wsrc[(co*96 + ci)*9 + kk];
        v1 = wsrc[(co*96 + ci + 1)*9 + kk];
    } else {
        int co = i / 48, k2 = i - co*48, ci = k2 << 1;
        v0 = wsrc[co*96 + ci];
        v1 = wsrc[co*96 + ci + 1];
    }
    uint32_t p0 = packsplit(v0), p1 = packsplit(v1);
    dh[i] = prmt(p0, p1, 0x5410);
    dl[i] = prmt(p0, p1, 0x7632);
}

// ---------------- split input tensor to packed form --------------------------
__global__ __launch_bounds__(256) void split_k(
    const float* __restrict__ x, uint32_t* __restrict__ xpk)
{
    int i = blockIdx.x*256 + threadIdx.x;
    if (i >= NPIX/4) return;
    float4 v = ((const float4*)x)[i];
    uint4 o;
    o.x = packsplit(v.x); o.y = packsplit(v.y);
    o.z = packsplit(v.z); o.w = packsplit(v.w);
    ((uint4*)xpk)[i] = o;
}

// ---------------- qkv weight fold (GN2 absorbed) -----------------------------
__global__ __launch_bounds__(256) void qfold_w_k(
    const float* __restrict__ qw, const float* __restrict__ stats,
    const float* __restrict__ ga)
{
    int i = blockIdx.x*256 + threadIdx.x;
    if (i >= 16*13824) return;
    int b = i / 13824, r = i - b*13824;
    int co = r / 48, k2 = r - co*48, ci = k2 << 1;
    float rstd = stats[(b*4 + ci/24)*2 + 1];
    float v0 = qw[co*96 + ci]     * rstd * ga[ci];
    float v1 = qw[co*96 + ci + 1] * rstd * ga[ci + 1];
    uint32_t p0 = packsplit(v0), p1 = packsplit(v1);
    g_qfh[i] = prmt(p0, p1, 0x5410);
    g_qfl[i] = prmt(p0, p1, 0x7632);
}

__global__ __launch_bounds__(256) void qfold_b_k(
    const float* __restrict__ qw, const float* __restrict__ qb,
    const float* __restrict__ stats, const float* __restrict__ ga,
    const float* __restrict__ ba)
{
    int j = blockIdx.x*256 + threadIdx.x;
    if (j >= 16*288) return;
    int b = j / 288, co = j - b*288;
    float s = qb[co];
#pragma unroll 4
    for (int ci = 0; ci < 96; ci++) {
        int g = ci / 24;
        float mean = stats[(b*4 + g)*2], rstd = stats[(b*4 + g)*2 + 1];
        float bet = ba[ci] - mean * rstd * ga[ci];
        s += qw[co*96 + ci] * bet;
    }
    g_qb2[j] = s;
}

// ---------------- conv3x3: packed staging + mma.sync -------------------------
// rowbuf stride 140 u32: col c -> idx c+4 (halo idx 3 & 132 stay zero).
#define C_ROW  0
#define C_BH   53760
#define C_BL   73728
#define C_BIAS 93696
#define CONV_SMEM 94080

__global__ __launch_bounds__(256) void conv3x3_mma_k(
    const uint32_t* __restrict__ inpk, const uint32_t* __restrict__ wphi,
    const uint32_t* __restrict__ wplo,
    const float* __restrict__ bias, float* __restrict__ out,
    float* __restrict__ part)
{
    extern __shared__ char smem[];
    uint32_t* rowbuf = (uint32_t*)(smem + C_ROW);
    uint32_t* sBhi   = (uint32_t*)(smem + C_BH);
    uint32_t* sBlo   = (uint32_t*)(smem + C_BL);
    float*    sbias  = (float*)(smem + C_BIAS);

    int tid = threadIdx.x, wid = tid >> 5, lane = tid & 31;
    int gid = lane >> 2, tig = lane & 3;
    int h = blockIdx.x, b = blockIdx.y;
    int m0 = (wid & 3) * 32;
    int n0 = (wid >> 2) * 48;

    float acc[12][4];
#pragma unroll
    for (int t = 0; t < 12; t++)
#pragma unroll
        for (int r = 0; r < 4; r++) acc[t][r] = 0.f;

    for (int i = tid; i < 96; i += 256) sbias[i] = bias[i];
    // halo slots + leading pads: always zero (image edge)
    for (int i = tid; i < 96; i += 256) {
        rowbuf[i*140 + 0] = 0; rowbuf[i*140 + 1] = 0;
        rowbuf[i*140 + 2] = 0; rowbuf[i*140 + 3] = 0;
        rowbuf[i*140 + 132] = 0;
    }

    for (int ky = 0; ky < 3; ky++) {
        int gh = h + ky - 1;
        __syncthreads();
        // A staging: pure uint4 copies of packed input (3072 quads)
        for (int i4 = tid; i4 < 3072; i4 += 256) {
            int ci = i4 >> 5, q = i4 & 31;
            uint4 v = make_uint4(0, 0, 0, 0);
            if ((unsigned)gh < 128u)
                v = *(const uint4*)&inpk[(((size_t)(b*96 + ci)) << 14)
                                         + (gh << 7) + (q << 2)];
            *(uint4*)&rowbuf[ci*140 + 4 + (q << 2)] = v;
        }

        for (int kx = 0; kx < 3; kx++) {
            __syncthreads();
            int kk = ky*3 + kx;
            for (int i4 = tid; i4 < 1152; i4 += 256) {
                int co = i4 / 12, k2 = (i4 - co*12) << 2;
                uint4 vh = *(const uint4*)&wphi[kk*4608 + co*48 + k2];
                uint4 vl = *(const uint4*)&wplo[kk*4608 + co*48 + k2];
                *(uint4*)&sBhi[co*52 + k2] = vh;
                *(uint4*)&sBlo[co*52 + k2] = vl;
            }
            __syncthreads();

#pragma unroll
            for (int kc = 0; kc < 6; kc++) {
                int ci0 = kc << 4;
                uint32_t ahi[8], alo[8];
#pragma unroll
                for (int mt = 0; mt < 2; mt++) {
                    int colIdx = m0 + mt*16 + gid + kx + 3;
#pragma unroll
                    for (int r = 0; r < 4; r++) {
                        int idx = (ci0 + (tig << 1) + ((r >> 1) << 3))*140
                                + colIdx + ((r & 1) << 3);
                        uint32_t v0 = rowbuf[idx];
                        uint32_t v1 = rowbuf[idx + 140];
                        ahi[mt*4 + r] = prmt(v0, v1, 0x5410);
                        alo[mt*4 + r] = prmt(v0, v1, 0x7632);
                    }
                }
                uint32_t bhi[12], blo[12];
#pragma unroll
                for (int nt = 0; nt < 6; nt++) {
                    int co = n0 + nt*8 + gid;
                    int k2 = (kc << 3) + tig;
                    bhi[nt*2]   = sBhi[co*52 + k2];
                    bhi[nt*2+1] = sBhi[co*52 + k2 + 4];
                    blo[nt*2]   = sBlo[co*52 + k2];
                    blo[nt*2+1] = sBlo[co*52 + k2 + 4];
                }
#pragma unroll
                for (int mt = 0; mt < 2; mt++)
#pragma unroll
                    for (int nt = 0; nt < 6; nt++) {
                        float* c = acc[mt*6 + nt];
                        mma16816(c, &ahi[mt*4], &bhi[nt*2]);
                        mma16816(c, &ahi[mt*4], &blo[nt*2]);
                        mma16816(c, &alo[mt*4], &bhi[nt*2]);
                    }
            }
        }
    }

    // epilogue: stores + per-group GN partials
    size_t obase = (((size_t)(b*96)) << 14) + (h << 7);
    float gs[2] = {0.f, 0.f}, gq[2] = {0.f, 0.f};
#pragma unroll
    for (int mt = 0; mt < 2; mt++) {
        int p = m0 + mt*16 + gid;
#pragma unroll
        for (int nt = 0; nt < 6; nt++) {
            int co = n0 + nt*8 + (tig << 1);
            float* c = acc[mt*6 + nt];
            float bs0 = sbias[co], bs1 = sbias[co+1];
            float v0 = c[0]+bs0, v1 = c[1]+bs1, v2 = c[2]+bs0, v3 = c[3]+bs1;
            out[obase + (((size_t)co)   << 14) + p]     = v0;
            out[obase + (((size_t)co+1) << 14) + p]     = v1;
            out[obase + (((size_t)co)   << 14) + p + 8] = v2;
            out[obase + (((size_t)co+1) << 14) + p + 8] = v3;
            int lg = nt / 3;
            gs[lg] += v0 + v1 + v2 + v3;
            gq[lg] += v0*v0 + v1*v1 + v2*v2 + v3*v3;
        }
    }
    __syncthreads();
    float* redS = (float*)(smem + C_BH);
    float* redQ = redS + 1024;
    int gb = (wid >> 2) * 2;
#pragma unroll
    for (int g = 0; g < 4; g++) {
        redS[g*256 + tid] = (g == gb) ? gs[0] : ((g == gb+1) ? gs[1] : 0.f);
        redQ[g*256 + tid] = (g == gb) ? gq[0] : ((g == gb+1) ? gq[1] : 0.f);
    }
    __syncthreads();
    for (int st = 128; st > 0; st >>= 1) {
        if (tid < st) {
#pragma unroll
            for (int g = 0; g < 4; g++) {
                redS[g*256 + tid] += redS[g*256 + tid + st];
                redQ[g*256 + tid] += redQ[g*256 + tid + st];
            }
        }
        __syncthreads();
    }
    if (tid < 4) {
        part[(b*4 + tid)*128 + h]        = redS[tid*256];
        part[8192 + (b*4 + tid)*128 + h] = redQ[tid*256];
    }
}

// ---------------- qkv 1x1: packed R + folded weights -------------------------
#define Q_ROW  0
#define Q_BH   50688
#define Q_BL   70656
#define Q_BIAS 90624
#define QKV_SMEM 91008

__global__ __launch_bounds__(256) void qkv_mma_k(
    const uint32_t* __restrict__ Rpk,
    const uint32_t* __restrict__ qfh, const uint32_t* __restrict__ qfl,
    const float* __restrict__ qb2, float* __restrict__ out)
{
    extern __shared__ char smem[];
    uint32_t* rowbuf = (uint32_t*)(smem + Q_ROW);
    uint32_t* sBhi   = (uint32_t*)(smem + Q_BH);
    uint32_t* sBlo   = (uint32_t*)(smem + Q_BL);
    float*    sbias  = (float*)(smem + Q_BIAS);

    int tid = threadIdx.x, wid = tid >> 5, lane = tid & 31;
    int gid = lane >> 2, tig = lane & 3;
    int h = blockIdx.x, cog = blockIdx.y, b = blockIdx.z;
    int m0 = (wid & 3) * 32;
    int n0 = (wid >> 2) * 48;

    float acc[12][4];
#pragma unroll
    for (int t = 0; t < 12; t++)
#pragma unroll
        for (int r = 0; r < 4; r++) acc[t][r] = 0.f;

    for (int i4 = tid; i4 < 3072; i4 += 256) {
        int ci = i4 >> 5, q = i4 & 31;
        uint4 v = *(const uint4*)&Rpk[(((size_t)(b*96 + ci)) << 14)
                                      + (h << 7) + (q << 2)];
        *(uint4*)&rowbuf[ci*132 + (q << 2)] = v;
    }
    for (int i4 = tid; i4 < 1152; i4 += 256) {
        int co = i4 / 12, k2 = (i4 - co*12) << 2;
        int base = b*13824 + cog*4608 + co*48 + k2;
        uint4 vh = *(const uint4*)&qfh[base];
        uint4 vl = *(const uint4*)&qfl[base];
        *(uint4*)&sBhi[co*52 + k2] = vh;
        *(uint4*)&sBlo[co*52 + k2] = vl;
    }
    for (int i = tid; i < 96; i += 256) sbias[i] = qb2[b*288 + cog*96 + i];
    __syncthreads();

#pragma unroll
    for (int kc = 0; kc < 6; kc++) {
        int ci0 = kc << 4;
        uint32_t ahi[8], alo[8];
#pragma unroll
        for (int mt = 0; mt < 2; mt++) {
            int colIdx = m0 + mt*16 + gid;
#pragma unroll
            for (int r = 0; r < 4; r++) {
                int idx = (ci0 + (tig << 1) + ((r >> 1) << 3))*132
                        + colIdx + ((r & 1) << 3);
                uint32_t v0 = rowbuf[idx];
                uint32_t v1 = rowbuf[idx + 132];
                ahi[mt*4 + r] = prmt(v0, v1, 0x5410);
                alo[mt*4 + r] = prmt(v0, v1, 0x7632);
            }
        }
        uint32_t bhi[12], blo[12];
#pragma unroll
        for (int nt = 0; nt < 6; nt++) {
            int co = n0 + nt*8 + gid;
            int k2 = (kc << 3) + tig;
            bhi[nt*2]   = sBhi[co*52 + k2];
            bhi[nt*2+1] = sBhi[co*52 + k2 + 4];
            blo[nt*2]   = sBlo[co*52 + k2];
            blo[nt*2+1] = sBlo[co*52 + k2 + 4];
        }
#pragma unroll
        for (int mt = 0; mt < 2; mt++)
#pragma unroll
            for (int nt = 0; nt < 6; nt++) {
                float* c = acc[mt*6 + nt];
                mma16816(c, &ahi[mt*4], &bhi[nt*2]);
                mma16816(c, &ahi[mt*4], &blo[nt*2]);
                mma16816(c, &alo[mt*4], &bhi[nt*2]);
            }
    }

    size_t obase = (((size_t)(b*288 + cog*96)) << 14) + (h << 7);
#pragma unroll
    for (int mt = 0; mt < 2; mt++) {
        int p = m0 + mt*16 + gid;
#pragma unroll
        for (int nt = 0; nt < 6; nt++) {
            int co = n0 + nt*8 + (tig << 1);
            float* c = acc[mt*6 + nt];
            float bs0 = sbias[co], bs1 = sbias[co+1];
            out[obase + (((size_t)co)   << 14) + p]     = c[0] + bs0;
            out[obase + (((size_t)co+1) << 14) + p]     = c[1] + bs1;
            out[obase + (((size_t)co)   << 14) + p + 8] = c[2] + bs0;
            out[obase + (((size_t)co+1) << 14) + p + 8] = c[3] + bs1;
        }
    }
}

// ---------------- proj 1x1 + residual; outputs packed A ----------------------
__global__ __launch_bounds__(256) void proj_mma_k(
    const float* __restrict__ o0, const float* __restrict__ o1,
    const uint32_t* __restrict__ Rpk,
    const uint32_t* __restrict__ pwhi, const uint32_t* __restrict__ pwlo,
    const float* __restrict__ pb, uint32_t* __restrict__ Apk)
{
    extern __shared__ char smem[];
    uint32_t* rowbuf = (uint32_t*)(smem + Q_ROW);
    uint32_t* sBhi   = (uint32_t*)(smem + Q_BH);
    uint32_t* sBlo   = (uint32_t*)(smem + Q_BL);
    float*    sbias  = (float*)(smem + Q_BIAS);

    int tid = threadIdx.x, wid = tid >> 5, lane = tid & 31;
    int gid = lane >> 2, tig = lane & 3;
    int h = blockIdx.x, b = blockIdx.y;
    int m0 = (wid & 3) * 32;
    int n0 = (wid >> 2) * 48;

    float acc[12][4];
#pragma unroll
    for (int t = 0; t < 12; t++)
#pragma unroll
        for (int r = 0; r < 4; r++) acc[t][r] = 0.f;

    for (int i = tid; i < 12288; i += 256) {
        int ci = i >> 7, col = i & 127;
        size_t idx = (((size_t)(b*96 + ci)) << 14) + (h << 7) + col;
        rowbuf[ci*132 + col] = packsplit(o0[idx] + o1[idx]);
    }
    for (int i4 = tid; i4 < 1152; i4 += 256) {
        int co = i4 / 12, k2 = (i4 - co*12) << 2;
        uint4 vh = *(const uint4*)&pwhi[co*48 + k2];
        uint4 vl = *(const uint4*)&pwlo[co*48 + k2];
        *(uint4*)&sBhi[co*52 + k2] = vh;
        *(uint4*)&sBlo[co*52 + k2] = vl;
    }
    for (int i = tid; i < 96; i += 256) sbias[i] = pb[i];
    __syncthreads();

#pragma unroll
    for (int kc = 0; kc < 6; kc++) {
        int ci0 = kc << 4;
        uint32_t ahi[8], alo[8];
#pragma unroll
        for (int mt = 0; mt < 2; mt++) {
            int colIdx = m0 + mt*16 + gid;
#pragma unroll
            for (int r = 0; r < 4; r++) {
                int idx = (ci0 + (tig << 1) + ((r >> 1) << 3))*132
                        + colIdx + ((r & 1) << 3);
                uint32_t v0 = rowbuf[idx];
                uint32_t v1 = rowbuf[idx + 132];
                ahi[mt*4 + r] = prmt(v0, v1, 0x5410);
                alo[mt*4 + r] = prmt(v0, v1, 0x7632);
            }
        }
        uint32_t bhi[12], blo[12];
#pragma unroll
        for (int nt = 0; nt < 6; nt++) {
            int co = n0 + nt*8 + gid;
            int k2 = (kc << 3) + tig;
            bhi[nt*2]   = sBhi[co*52 + k2];
            bhi[nt*2+1] = sBhi[co*52 + k2 + 4];
            blo[nt*2]   = sBlo[co*52 + k2];
            blo[nt*2+1] = sBlo[co*52 + k2 + 4];
        }
#pragma unroll
        for (int mt = 0; mt < 2; mt++)
#pragma unroll
            for (int nt = 0; nt < 6; nt++) {
                float* c = acc[mt*6 + nt];
                mma16816(c, &ahi[mt*4], &bhi[nt*2]);
                mma16816(c, &ahi[mt*4], &blo[nt*2]);
                mma16816(c, &alo[mt*4], &bhi[nt*2]);
            }
    }

    size_t obase = (((size_t)(b*96)) << 14) + (h << 7);
#pragma unroll
    for (int mt = 0; mt < 2; mt++) {
        int p = m0 + mt*16 + gid;
#pragma unroll
        for (int nt = 0; nt < 6; nt++) {
            int co = n0 + nt*8 + (tig << 1);
            float* c = acc[mt*6 + nt];
            float bs0 = sbias[co], bs1 = sbias[co+1];
            size_t i00 = obase + (((size_t)co) << 14) + p;
            size_t i10 = obase + (((size_t)co+1) << 14) + p;
            Apk[i00]     = packsplit(unpacksum(Rpk[i00])     + 0.5f*c[0] + bs0);
            Apk[i10]     = packsplit(unpacksum(Rpk[i10])     + 0.5f*c[1] + bs1);
            Apk[i00 + 8] = packsplit(unpacksum(Rpk[i00 + 8]) + 0.5f*c[2] + bs0);
            Apk[i10 + 8] = packsplit(unpacksum(Rpk[i10 + 8]) + 0.5f*c[3] + bs1);
        }
    }
}

// ---------------- GN finalize ------------------------------------------------
__global__ void gn_finalize_k(const float* __restrict__ part, int nch, int sqoff,
                              float* __restrict__ stats)
{
    int bg = threadIdx.x;
    float s = 0, q = 0;
    for (int c = 0; c < nch; c++) {
        s += part[bg*nch + c];
        q += part[sqoff + bg*nch + c];
    }
    float mean = s * (1.f/393216.f);
    float var  = q * (1.f/393216.f) - mean*mean;
    stats[bg*2 + 0] = mean;
    stats[bg*2 + 1] = rsqrtf(var + 1e-5f);
}

// ---------------- time-embedding MLP -----------------------------------------
__global__ void temb_k(const float* __restrict__ te, const float* __restrict__ wt,
                       const float* __restrict__ bt, float* __restrict__ film)
{
    __shared__ float sh[256];
    int b = blockIdx.x, j = blockIdx.y*32 + threadIdx.x;
    for (int i = threadIdx.x; i < 256; i += 32) sh[i] = te[b*256 + i];
    __syncthreads();
    const float* wr = wt + j*256;
    float s = bt[j];
#pragma unroll 4
    for (int k = 0; k < 256; k++) s += sh[k]*wr[k];
    s = s / (1.f + expf(-s));
    film[b*192 + j] = s;
}

// ---------------- apply GN1+SiLU+FiLM -> packed R + GN2 partials -------------
__global__ __launch_bounds__(256) void apply1_k(
    const float* __restrict__ x, const float* __restrict__ stats,
    const float* __restrict__ g1, const float* __restrict__ be1,
    const float* __restrict__ film, uint32_t* __restrict__ Rpk,
    float* __restrict__ part)
{
    int bg = blockIdx.x, chunk = blockIdx.y;
    int b = bg >> 2, g = bg & 3;
    int tid = threadIdx.x;
    size_t base = (size_t)bg*GN_N + (size_t)chunk*49152;
    float mean = stats[bg*2], rstd = stats[bg*2+1];
    const float4* xp = (const float4*)(x + base);
    uint4* op = (uint4*)(Rpk + base);

    float sx=0, sy=0, sz=0, sw=0, qx=0, qy=0, qz=0, qw=0;
    for (int i = tid; i < 12288; i += 256) {
        int c = g*24 + chunk*3 + (i >> 12);
        float gam = g1[c]*rstd;
        float bet = be1[c] - mean*gam;
        float shf = 1.f + film[b*192 + c];
        float bia = film[b*192 + 96 + c];
        float4 v = xp[i];
        float t;
        t = v.x*gam + bet; t = t/(1.f+expf(-t)); v.x = t*shf + bia;
        t = v.y*gam + bet; t = t/(1.f+expf(-t)); v.y = t*shf + bia;
        t = v.z*gam + bet; t = t/(1.f+expf(-t)); v.z = t*shf + bia;
        t = v.w*gam + bet; t = t/(1.f+expf(-t)); v.w = t*shf + bia;
        uint4 o;
        o.x = packsplit(v.x); o.y = packsplit(v.y);
        o.z = packsplit(v.z); o.w = packsplit(v.w);
        op[i] = o;
        sx += v.x; sy += v.y; sz += v.z; sw += v.w;
        qx += v.x*v.x; qy += v.y*v.y; qz += v.z*v.z; qw += v.w*v.w;
    }
    __shared__ double sh[512];
    sh[tid]       = (double)sx + sy + sz + sw;
    sh[256 + tid] = (double)qx + qy + qz + qw;
    __syncthreads();
    for (int st = 128; st > 0; st >>= 1) {
        if (tid < st) { sh[tid] += sh[tid+st]; sh[256+tid] += sh[256+tid+st]; }
        __syncthreads();
    }
    if (tid == 0) {
        part[bg*8 + chunk]       = (float)sh[0];
        part[512 + bg*8 + chunk] = (float)sh[256];
    }
}

// ---------------- final: SiLU(GN(conv2)) -> d_out ----------------------------
__global__ __launch_bounds__(256) void apply3_k(
    const float* __restrict__ x, const float* __restrict__ stats,
    const float* __restrict__ g2, const float* __restrict__ be2,
    float* __restrict__ out)
{
    int idx4 = blockIdx.x*256 + threadIdx.x;
    if (idx4 >= NPIX/4) return;
    int flat = idx4 << 2;
    int cimg = flat >> 14;
    int b = cimg / 96, c = cimg - 96*b;
    int bg = b*4 + c/24;
    float mean = stats[bg*2], rstd = stats[bg*2+1];
    float gam = g2[c]*rstd;
    float bet = be2[c] - mean*gam;
    float4 v = *(const float4*)&x[flat];
    float t;
    t = v.x*gam + bet; v.x = t/(1.f+expf(-t));
    t = v.y*gam + bet; v.y = t/(1.f+expf(-t));
    t = v.z*gam + bet; v.z = t/(1.f+expf(-t));
    t = v.w*gam + bet; v.w = t/(1.f+expf(-t));
    *(float4*)&out[flat] = v;
}

// ---------------- attention core ---------------------------------------------
__global__ __launch_bounds__(256) void attn_core_k(
    const float* __restrict__ qkv, float* __restrict__ o0, float* __restrict__ o1)
{
    extern __shared__ float sm[];
    float* sq   = sm;
    float* slog = sq + 18432;
    float* spr  = slog + 576;

    int b = blockIdx.y, branch = blockIdx.z;
    int hn = blockIdx.x >> 4, wn = blockIdx.x & 15;
    int sh = branch*4;
    int h0 = hn*8 + sh, w0 = wn*8 + sh;
    int tid = threadIdx.x;

    for (int i = tid; i < 4608; i += 256) {
        int c = i >> 4, lq = i & 15, l = lq << 2;
        int gh = (h0 + (l >> 3)) & 127, gw = (w0 + (l & 7)) & 127;
        *(float4*)&sq[(c << 6) + l] =
            *(const float4*)&qkv[(((size_t)(b*288 + c)) << 14) + (gh << 7) + gw];
    }
    __syncthreads();

    const float scale = 0.40824829046386307f;
    for (int i = tid; i < 576; i += 256) {
        int head = i / 36, r = i - head*36, d = r / 6, e = r - d*6;
        const float* qp = &sq[(head*6 + d) << 6];
        const float* kp = &sq[(96 + head*6 + e) << 6];
        float a = 0.f;
#pragma unroll 8
        for (int l = 0; l < 64; l++) a += qp[l]*kp[l];
        slog[i] = a*scale;
    }
    __syncthreads();

    if (tid < 96) {
        int head = tid / 6, d = tid - head*6, base = head*36 + d*6;
        float m = -1e30f;
#pragma unroll
        for (int e = 0; e < 6; e++) m = fmaxf(m, slog[base+e]);
        float ex[6]; float s = 0.f;
#pragma unroll
        for (int e = 0; e < 6; e++) { ex[e] = expf(slog[base+e] - m); s += ex[e]; }
        float inv = 1.f/s;
#pragma unroll
        for (int e = 0; e < 6; e++) spr[base+e] = ex[e]*inv;
    }
    __syncthreads();

    float* o = branch ? o1 : o0;
    for (int i = tid; i < 1536; i += 256) {
        int ch = i >> 4, lq = i & 15, l = lq << 2;
        int head = ch / 6, d = ch - head*6;
        float4 a = {0.f, 0.f, 0.f, 0.f};
#pragma unroll
        for (int e = 0; e < 6; e++) {
            float p = spr[head*36 + d*6 + e];
            float4 vv = *(const float4*)&sq[((192 + head*6 + e) << 6) + l];
            a.x += p*vv.x; a.y += p*vv.y; a.z += p*vv.z; a.w += p*vv.w;
        }
        int gh = (h0 + (l >> 3)) & 127, gw = (w0 + (l & 7)) & 127;
        *(float4*)&o[(((size_t)(b*96 + ch)) << 14) + (gh << 7) + gw] = a;
    }
}

// ---------------- launch -----------------------------------------------------
extern "C" void kernel_launch(void* const* d_in, const int* in_sizes, int n_in,
                              void* d_out, int out_size)
{
    const float* x      = (const float*)d_in[0];
    const float* t_emb  = (const float*)d_in[1];
    const float* w1     = (const float*)d_in[2];
    const float* b1     = (const float*)d_in[3];
    const float* g1     = (const float*)d_in[4];
    const float* be1    = (const float*)d_in[5];
    const float* wt     = (const float*)d_in[6];
    const float* bt     = (const float*)d_in[7];
    const float* qkv_w  = (const float*)d_in[8];
    const float* qkv_b  = (const float*)d_in[9];
    const float* proj_w = (const float*)d_in[10];
    const float* proj_b = (const float*)d_in[11];
    const float* ga     = (const float*)d_in[12];
    const float* ba     = (const float*)d_in[13];
    const float* w2     = (const float*)d_in[14];
    const float* b2     = (const float*)d_in[15];
    const float* g2     = (const float*)d_in[16];
    const float* be2    = (const float*)d_in[17];
    float* out = (float*)d_out;

    uint32_t *xpk, *Rpk, *Apk, *w1hi, *w1lo, *w2hi, *w2lo, *pwhi, *pwlo;
    uint32_t *qfh, *qfl;
    float *buf1, *buf4, *qkvb, *part0, *part1, *part2, *stats, *film, *qb2;
    cudaGetSymbolAddress((void**)&xpk,  g_xpk);
    cudaGetSymbolAddress((void**)&Rpk,  g_Rpk);
    cudaGetSymbolAddress((void**)&Apk,  g_Apk);
    cudaGetSymbolAddress((void**)&buf1, g_buf1);
    cudaGetSymbolAddress((void**)&buf4, g_buf4);
    cudaGetSymbolAddress((void**)&qkvb, g_qkv);
    cudaGetSymbolAddress((void**)&part0, g_part0);
    cudaGetSymbolAddress((void**)&part1, g_part1);
    cudaGetSymbolAddress((void**)&part2, g_part2);
    cudaGetSymbolAddress((void**)&stats, g_stats);
    cudaGetSymbolAddress((void**)&film, g_film);
    cudaGetSymbolAddress((void**)&w1hi, g_w1hi);
    cudaGetSymbolAddress((void**)&w1lo, g_w1lo);
    cudaGetSymbolAddress((void**)&w2hi, g_w2hi);
    cudaGetSymbolAddress((void**)&w2lo, g_w2lo);
    cudaGetSymbolAddress((void**)&pwhi, g_pwhi);
    cudaGetSymbolAddress((void**)&pwlo, g_pwlo);
    cudaGetSymbolAddress((void**)&qfh,  g_qfh);
    cudaGetSymbolAddress((void**)&qfl,  g_qfl);
    cudaGetSymbolAddress((void**)&qb2,  g_qb2);

    const int ATTN_SMEM = (18432 + 576 + 576) * 4;
    cudaFuncSetAttribute(attn_core_k, cudaFuncAttributeMaxDynamicSharedMemorySize,
                         ATTN_SMEM);
    cudaFuncSetAttribute(conv3x3_mma_k, cudaFuncAttributeMaxDynamicSharedMemorySize,
                         CONV_SMEM);
    cudaFuncSetAttribute(qkv_mma_k, cudaFuncAttributeMaxDynamicSharedMemorySize,
                         QKV_SMEM);
    cudaFuncSetAttribute(proj_mma_k, cudaFuncAttributeMaxDynamicSharedMemorySize,
                         QKV_SMEM);

    dim3 cgrid(128, 16);

    prep_k<<<162, 256>>>(w1, w1hi, w1lo, 41472, 1);
    prep_k<<<162, 256>>>(w2, w2hi, w2lo, 41472, 1);
    prep_k<<<18, 256>>>(proj_w, pwhi, pwlo, 4608, 0);
    temb_k<<<dim3(16, 6), 32>>>(t_emb, wt, bt, film);
    split_k<<<NPIX/4/256, 256>>>(x, xpk);
    conv3x3_mma_k<<<cgrid, 256, CONV_SMEM>>>(xpk, w1hi, w1lo, b1, buf1, part0);
    gn_finalize_k<<<1, 64>>>(part0, 128, 8192, stats + 0*128);
    apply1_k<<<dim3(64, 8), 256>>>(buf1, stats + 0*128, g1, be1, film, Rpk, part1);
    gn_finalize_k<<<1, 64>>>(part1, 8, 512, stats + 1*128);
    qfold_w_k<<<864, 256>>>(qkv_w, stats + 1*128, ga);
    qfold_b_k<<<18, 256>>>(qkv_w, qkv_b, stats + 1*128, ga, ba);
    qkv_mma_k<<<dim3(128, 3, 16), 256, QKV_SMEM>>>(Rpk, qfh, qfl, qb2, qkvb);
    attn_core_k<<<dim3(256, 16, 2), 256, ATTN_SMEM>>>(qkvb, buf1, buf4);
    proj_mma_k<<<cgrid, 256, QKV_SMEM>>>(buf1, buf4, Rpk, pwhi, pwlo,
                                         proj_b, Apk);
    conv3x3_mma_k<<<cgrid, 256, CONV_SMEM>>>(Apk, w2hi, w2lo, b2, buf1, part2);
    gn_finalize_k<<<1, 64>>>(part2, 128, 8192, stats + 2*128);
    apply3_k<<<NPIX/4/256, 256>>>(buf1, stats + 2*128, g2, be2, out);
}

// round 12
// speedup vs baseline: 1.2418x; 1.2418x over previous
#include <cuda_runtime.h>
#include <cuda_bf16.h>
#include <math.h>
#include <stdint.h>

#define NPIX (16*96*16384)
#define GN_N 393216

// ---------------- scratch ----------------------------------------------------
__device__ float g_buf1[NPIX];
__device__ float g_buf2[NPIX];
__device__ float g_buf3[NPIX];
__device__ float g_buf4[NPIX];
__device__ float g_qkv[3*NPIX];
__device__ float g_part0[16384];
__device__ float g_part1[1024];
__device__ float g_part2[16384];
__device__ float g_stats[3*64*2];
__device__ float g_film[16*192];
__device__ uint32_t g_w1hi[41472], g_w1lo[41472];
__device__ uint32_t g_w2hi[41472], g_w2lo[41472];
__device__ uint32_t g_qwhi[13824], g_qwlo[13824];
__device__ uint32_t g_pwhi[4608],  g_pwlo[4608];

// ---------------- helpers ----------------------------------------------------
__device__ __forceinline__ uint32_t smem_u32(const void* p) {
    uint32_t a;
    asm("{ .reg .u64 t; cvta.to.shared.u64 t, %1; cvt.u32.u64 %0, t; }"
        : "=r"(a) : "l"(p));
    return a;
}
__device__ __forceinline__ void mma16816(float* c, const uint32_t* a,
                                         const uint32_t* b) {
    asm volatile(
        "mma.sync.aligned.m16n8k16.row.col.f32.bf16.bf16.f32 "
        "{%0,%1,%2,%3}, {%4,%5,%6,%7}, {%8,%9}, {%0,%1,%2,%3};"
        : "+f"(c[0]), "+f"(c[1]), "+f"(c[2]), "+f"(c[3])
        : "r"(a[0]), "r"(a[1]), "r"(a[2]), "r"(a[3]), "r"(b[0]), "r"(b[1]));
}
__device__ __forceinline__ void ldsm4(uint32_t* r, uint32_t a) {
    asm volatile("ldmatrix.sync.aligned.m8n8.x4.shared.b16 {%0,%1,%2,%3}, [%4];"
        : "=r"(r[0]), "=r"(r[1]), "=r"(r[2]), "=r"(r[3]) : "r"(a));
}
__device__ __forceinline__ void bsplit(float v, unsigned short& h,
                                       unsigned short& l) {
    __nv_bfloat16 hv = __float2bfloat16(v);
    __nv_bfloat16 lv = __float2bfloat16(v - __bfloat162float(hv));
    h = __bfloat16_as_ushort(hv);
    l = __bfloat16_as_ushort(lv);
}
__device__ __forceinline__ void cpa16(uint32_t s, const void* g) {
    asm volatile("cp.async.ca.shared.global [%0], [%1], 16;"
                 :: "r"(s), "l"(g) : "memory");
}
#define CP_COMMIT() asm volatile("cp.async.commit_group;" ::: "memory")
#define CP_WAIT0()  asm volatile("cp.async.wait_group 0;" ::: "memory")
#define CP_WAIT1()  asm volatile("cp.async.wait_group 1;" ::: "memory")

// ---------------- weight prepack ---------------------------------------------
__global__ __launch_bounds__(256) void prep_k(
    const float* __restrict__ wsrc, uint32_t* __restrict__ dh,
    uint32_t* __restrict__ dl, int n, int is33)
{
    int i = blockIdx.x*256 + threadIdx.x;
    if (i >= n) return;
    float v0, v1;
    if (is33) {
        int kk = i / 4608, r = i - kk*4608;
        int co = r / 48, k2 = r - co*48, ci = k2 << 1;
        v0 = wsrc[(co*96 + ci)*9 + kk];
        v1 = wsrc[(co*96 + ci + 1)*9 + kk];
    } else {
        int co = i / 48, k2 = i - co*48, ci = k2 << 1;
        v0 = wsrc[co*96 + ci];
        v1 = wsrc[co*96 + ci + 1];
    }
    unsigned short h0, l0, h1, l1;
    bsplit(v0, h0, l0);
    bsplit(v1, h1, l1);
    dh[i] = (uint32_t)h0 | ((uint32_t)h1 << 16);
    dl[i] = (uint32_t)l0 | ((uint32_t)l1 << 16);
}

// ---------------- conv3x3: 512 threads, cp.async double-buffered B -----------
#define PS  104
#define PS2 208
#define C_AH   0                     // u16 sAh [130 cols x 104]   27,072 B
#define C_AL   27072                 // u16 sAl                    27,072 B
#define C_B    54144                 // 2 bufs x (Bhi 19968 + Blo 19968)
#define C_BIAS 134016
#define CONV_SMEM 134400

__global__ __launch_bounds__(512) void conv3x3_mma_k(
    const float* __restrict__ in, const uint32_t* __restrict__ wphi,
    const uint32_t* __restrict__ wplo,
    const float* __restrict__ bias, float* __restrict__ out,
    float* __restrict__ part)
{
    extern __shared__ char smem[];
    uint32_t sb = smem_u32(smem);
    unsigned short* sAh = (unsigned short*)(smem + C_AH);
    unsigned short* sAl = (unsigned short*)(smem + C_AL);
    float* sbias = (float*)(smem + C_BIAS);

    int tid = threadIdx.x, wid = tid >> 5, lane = tid & 31;
    int gid = lane >> 2, tig = lane & 3;
    int h = blockIdx.x, b = blockIdx.y;
    int m0 = (wid & 3) * 32;
    int n0 = (wid >> 2) * 24;

    float acc[6][4];
#pragma unroll
    for (int t = 0; t < 6; t++)
#pragma unroll
        for (int r = 0; r < 4; r++) acc[t][r] = 0.f;

    for (int i = tid; i < 96; i += 512) sbias[i] = bias[i];

    uint32_t aH = sb + C_AH + (uint32_t)((((m0 + (lane & 15))*PS) + ((lane >> 4) << 3)) << 1);
    uint32_t aL = aH + (C_AL - C_AH);

    // prologue: prefetch B(0) into buf 0
    {
        uint32_t bb = sb + C_B;
        for (int i4 = tid; i4 < 1152; i4 += 512) {
            int co = i4 / 12, k2 = (i4 - co*12) << 2;
            uint32_t so = (uint32_t)((co*52 + k2) << 2);
            cpa16(bb + so,         &wphi[co*48 + k2]);
            cpa16(bb + 19968 + so, &wplo[co*48 + k2]);
        }
        CP_COMMIT();
    }

    for (int ky = 0; ky < 3; ky++) {
        int gh = h + ky - 1;
        __syncthreads();                       // prev-ky A readers done
        for (int i = tid; i < 12480; i += 512) {
            int ci = i / 130, col = i - ci*130;
            int gw = col - 1;
            float v = 0.f;
            if ((unsigned)gh < 128u && (unsigned)gw < 128u)
                v = in[(((size_t)(b*96 + ci)) << 14) + (gh << 7) + gw];
            unsigned short hv, lv;
            bsplit(v, hv, lv);
            int a = col*PS + ci;
            sAh[a] = hv;
            sAl[a] = lv;
        }
        __syncthreads();                       // A staged (also: all warps past
                                               // reading B buf being prefetched)
        for (int kx = 0; kx < 3; kx++) {
            int kk = ky*3 + kx;
            // issue prefetch for kk+1 (buffer read last in phase kk-1;
            // the sync above / end-of-phase sync guarantees safety)
            if (kk < 8) {
                uint32_t bb = sb + C_B + (uint32_t)(((kk + 1) & 1) * 39936);
                const uint32_t* ph = wphi + (kk + 1)*4608;
                const uint32_t* pl = wplo + (kk + 1)*4608;
                for (int i4 = tid; i4 < 1152; i4 += 512) {
                    int co = i4 / 12, k2 = (i4 - co*12) << 2;
                    uint32_t so = (uint32_t)((co*52 + k2) << 2);
                    cpa16(bb + so,         ph + co*48 + k2);
                    cpa16(bb + 19968 + so, pl + co*48 + k2);
                }
                CP_COMMIT();
                CP_WAIT1();                    // B(kk) group complete
            } else {
                CP_WAIT0();
            }
            __syncthreads();                   // B(kk) visible to all

            uint32_t* sBhi = (uint32_t*)(smem + C_B + (kk & 1)*39936);
            uint32_t* sBlo = sBhi + 4992;      // 19,968 B
            uint32_t aox = (uint32_t)(kx*PS2);
#pragma unroll
            for (int kc = 0; kc < 6; kc++) {
                uint32_t ahi[8], alo[8];
                ldsm4(ahi,     aH + aox + kc*32);
                ldsm4(ahi + 4, aH + aox + 16*PS2 + kc*32);
                ldsm4(alo,     aL + aox + kc*32);
                ldsm4(alo + 4, aL + aox + 16*PS2 + kc*32);
                uint32_t bhi[6], blo[6];
#pragma unroll
                for (int nt = 0; nt < 3; nt++) {
                    int co = n0 + nt*8 + gid;
                    int k2 = (kc << 3) + tig;
                    bhi[nt*2]   = sBhi[co*52 + k2];
                    bhi[nt*2+1] = sBhi[co*52 + k2 + 4];
                    blo[nt*2]   = sBlo[co*52 + k2];
                    blo[nt*2+1] = sBlo[co*52 + k2 + 4];
                }
#pragma unroll
                for (int mt = 0; mt < 2; mt++)
#pragma unroll
                    for (int nt = 0; nt < 3; nt++) {
                        float* c = acc[mt*3 + nt];
                        mma16816(c, &ahi[mt*4], &bhi[nt*2]);
                        mma16816(c, &ahi[mt*4], &blo[nt*2]);
                        mma16816(c, &alo[mt*4], &bhi[nt*2]);
                    }
            }
            __syncthreads();                   // compute done before next issue
        }
    }

    // epilogue: stores + per-group GN partials
    size_t obase = (((size_t)(b*96)) << 14) + (h << 7);
    float gs = 0.f, gq = 0.f;
    int gg = wid >> 2;                         // global group of this warp
#pragma unroll
    for (int mt = 0; mt < 2; mt++) {
        int p = m0 + mt*16 + gid;
#pragma unroll
        for (int nt = 0; nt < 3; nt++) {
            int co = n0 + nt*8 + (tig << 1);
            float* c = acc[mt*3 + nt];
            float bs0 = sbias[co], bs1 = sbias[co+1];
            float v0 = c[0]+bs0, v1 = c[1]+bs1, v2 = c[2]+bs0, v3 = c[3]+bs1;
            out[obase + (((size_t)co)   << 14) + p]     = v0;
            out[obase + (((size_t)co+1) << 14) + p]     = v1;
            out[obase + (((size_t)co)   << 14) + p + 8] = v2;
            out[obase + (((size_t)co+1) << 14) + p + 8] = v3;
            gs += v0 + v1 + v2 + v3;
            gq += v0*v0 + v1*v1 + v2*v2 + v3*v3;
        }
    }
    __syncthreads();                           // B area free for reuse
    float* redS = (float*)(smem + C_B);        // [4][512]
    float* redQ = redS + 2048;
#pragma unroll
    for (int g = 0; g < 4; g++) {
        redS[g*512 + tid] = (g == gg) ? gs : 0.f;
        redQ[g*512 + tid] = (g == gg) ? gq : 0.f;
    }
    __syncthreads();
    for (int st = 256; st > 0; st >>= 1) {
        if (tid < st) {
#pragma unroll
            for (int g = 0; g < 4; g++) {
                redS[g*512 + tid] += redS[g*512 + tid + st];
                redQ[g*512 + tid] += redQ[g*512 + tid + st];
            }
        }
        __syncthreads();
    }
    if (tid < 4) {
        part[(b*4 + tid)*128 + h]        = redS[tid*512];
        part[8192 + (b*4 + tid)*128 + h] = redQ[tid*512];
    }
}

// ---------------- qkv 1x1 via mma.sync + ldmatrix (GN2 fused) ----------------
#define Q_AH   0
#define Q_AL   26624
#define Q_BH   53248
#define Q_BL   73216
#define Q_BIAS 93184
#define QKV_SMEM (93184 + 384)

__global__ __launch_bounds__(256) void qkv_mma_k(
    const float* __restrict__ R, const float* __restrict__ stats,
    const float* __restrict__ ga, const float* __restrict__ ba,
    const uint32_t* __restrict__ qwhi, const uint32_t* __restrict__ qwlo,
    const float* __restrict__ qb, float* __restrict__ out)
{
    extern __shared__ char smem[];
    uint32_t sb = smem_u32(smem);
    unsigned short* sAh = (unsigned short*)(smem + Q_AH);
    unsigned short* sAl = (unsigned short*)(smem + Q_AL);
    float* sbias = (float*)(smem + Q_BIAS);

    int tid = threadIdx.x, wid = tid >> 5, lane = tid & 31;
    int gid = lane >> 2, tig = lane & 3;
    int h = blockIdx.x, cog = blockIdx.y, b = blockIdx.z;
    int m0 = (wid & 3) * 32;
    int n0 = (wid >> 2) * 48;

    float acc[12][4];
#pragma unroll
    for (int t = 0; t < 12; t++)
#pragma unroll
        for (int r = 0; r < 4; r++) acc[t][r] = 0.f;

    // B via cp.async first (latency overlaps A conversion below)
    for (int i4 = tid; i4 < 1152; i4 += 256) {
        int co = i4 / 12, k2 = (i4 - co*12) << 2;
        uint32_t so = (uint32_t)((co*52 + k2) << 2);
        cpa16(sb + Q_BH + so, &qwhi[cog*4608 + co*48 + k2]);
        cpa16(sb + Q_BL + so, &qwlo[cog*4608 + co*48 + k2]);
    }
    CP_COMMIT();

    for (int i = tid; i < 12288; i += 256) {
        int ci = i >> 7, col = i & 127;
        int bg = b*4 + ci/24;
        float v = R[(((size_t)(b*96 + ci)) << 14) + (h << 7) + col];
        float xn = (v - stats[bg*2])*stats[bg*2+1]*ga[ci] + ba[ci];
        unsigned short hv, lv;
        bsplit(xn, hv, lv);
        int a = col*PS + ci;
        sAh[a] = hv;
        sAl[a] = lv;
    }
    for (int i = tid; i < 96; i += 256) sbias[i] = qb[cog*96 + i];
    CP_WAIT0();
    __syncthreads();

    uint32_t* sBhi = (uint32_t*)(smem + Q_BH);
    uint32_t* sBlo = (uint32_t*)(smem + Q_BL);
    uint32_t aH = sb + Q_AH + (uint32_t)((((m0 + (lane & 15))*PS) + ((lane >> 4) << 3)) << 1);
    uint32_t aL = aH + (Q_AL - Q_AH);

#pragma unroll
    for (int kc = 0; kc < 6; kc++) {
        uint32_t ahi[8], alo[8];
        ldsm4(ahi,     aH + kc*32);
        ldsm4(ahi + 4, aH + 16*PS2 + kc*32);
        ldsm4(alo,     aL + kc*32);
        ldsm4(alo + 4, aL + 16*PS2 + kc*32);
        uint32_t bhi[12], blo[12];
#pragma unroll
        for (int nt = 0; nt < 6; nt++) {
            int co = n0 + nt*8 + gid;
            int k2 = (kc << 3) + tig;
            bhi[nt*2]   = sBhi[co*52 + k2];
            bhi[nt*2+1] = sBhi[co*52 + k2 + 4];
            blo[nt*2]   = sBlo[co*52 + k2];
            blo[nt*2+1] = sBlo[co*52 + k2 + 4];
        }
#pragma unroll
        for (int mt = 0; mt < 2; mt++)
#pragma unroll
            for (int nt = 0; nt < 6; nt++) {
                float* c = acc[mt*6 + nt];
                mma16816(c, &ahi[mt*4], &bhi[nt*2]);
                mma16816(c, &ahi[mt*4], &blo[nt*2]);
                mma16816(c, &alo[mt*4], &bhi[nt*2]);
            }
    }

    size_t obase = (((size_t)(b*288 + cog*96)) << 14) + (h << 7);
#pragma unroll
    for (int mt = 0; mt < 2; mt++) {
        int p = m0 + mt*16 + gid;
#pragma unroll
        for (int nt = 0; nt < 6; nt++) {
            int co = n0 + nt*8 + (tig << 1);
            float* c = acc[mt*6 + nt];
            float bs0 = sbias[co], bs1 = sbias[co+1];
            out[obase + (((size_t)co)   << 14) + p]     = c[0] + bs0;
            out[obase + (((size_t)co+1) << 14) + p]     = c[1] + bs1;
            out[obase + (((size_t)co)   << 14) + p + 8] = c[2] + bs0;
            out[obase + (((size_t)co+1) << 14) + p + 8] = c[3] + bs1;
        }
    }
}

// ---------------- proj 1x1 via mma.sync + ldmatrix + residual ----------------
__global__ __launch_bounds__(256) void proj_mma_k(
    const float* __restrict__ o0, const float* __restrict__ o1,
    const float* __restrict__ R,
    const uint32_t* __restrict__ pwhi, const uint32_t* __restrict__ pwlo,
    const float* __restrict__ pb, float* __restrict__ A)
{
    extern __shared__ char smem[];
    uint32_t sb = smem_u32(smem);
    unsigned short* sAh = (unsigned short*)(smem + Q_AH);
    unsigned short* sAl = (unsigned short*)(smem + Q_AL);
    float* sbias = (float*)(smem + Q_BIAS);

    int tid = threadIdx.x, wid = tid >> 5, lane = tid & 31;
    int gid = lane >> 2, tig = lane & 3;
    int h = blockIdx.x, b = blockIdx.y;
    int m0 = (wid & 3) * 32;
    int n0 = (wid >> 2) * 48;

    float acc[12][4];
#pragma unroll
    for (int t = 0; t < 12; t++)
#pragma unroll
        for (int r = 0; r < 4; r++) acc[t][r] = 0.f;

    for (int i4 = tid; i4 < 1152; i4 += 256) {
        int co = i4 / 12, k2 = (i4 - co*12) << 2;
        uint32_t so = (uint32_t)((co*52 + k2) << 2);
        cpa16(sb + Q_BH + so, &pwhi[co*48 + k2]);
        cpa16(sb + Q_BL + so, &pwlo[co*48 + k2]);
    }
    CP_COMMIT();

    for (int i = tid; i < 12288; i += 256) {
        int ci = i >> 7, col = i & 127;
        size_t idx = (((size_t)(b*96 + ci)) << 14) + (h << 7) + col;
        float v = o0[idx] + o1[idx];
        unsigned short hv, lv;
        bsplit(v, hv, lv);
        int a = col*PS + ci;
        sAh[a] = hv;
        sAl[a] = lv;
    }
    for (int i = tid; i < 96; i += 256) sbias[i] = pb[i];
    CP_WAIT0();
    __syncthreads();

    uint32_t* sBhi = (uint32_t*)(smem + Q_BH);
    uint32_t* sBlo = (uint32_t*)(smem + Q_BL);
    uint32_t aH = sb + Q_AH + (uint32_t)((((m0 + (lane & 15))*PS) + ((lane >> 4) << 3)) << 1);
    uint32_t aL = aH + (Q_AL - Q_AH);

#pragma unroll
    for (int kc = 0; kc < 6; kc++) {
        uint32_t ahi[8], alo[8];
        ldsm4(ahi,     aH + kc*32);
        ldsm4(ahi + 4, aH + 16*PS2 + kc*32);
        ldsm4(alo,     aL + kc*32);
        ldsm4(alo + 4, aL + 16*PS2 + kc*32);
        uint32_t bhi[12], blo[12];
#pragma unroll
        for (int nt = 0; nt < 6; nt++) {
            int co = n0 + nt*8 + gid;
            int k2 = (kc << 3) + tig;
            bhi[nt*2]   = sBhi[co*52 + k2];
            bhi[nt*2+1] = sBhi[co*52 + k2 + 4];
            blo[nt*2]   = sBlo[co*52 + k2];
            blo[nt*2+1] = sBlo[co*52 + k2 + 4];
        }
#pragma unroll
        for (int mt = 0; mt < 2; mt++)
#pragma unroll
            for (int nt = 0; nt < 6; nt++) {
                float* c = acc[mt*6 + nt];
                mma16816(c, &ahi[mt*4], &bhi[nt*2]);
                mma16816(c, &ahi[mt*4], &blo[nt*2]);
                mma16816(c, &alo[mt*4], &bhi[nt*2]);
            }
    }

    size_t obase = (((size_t)(b*96)) << 14) + (h << 7);
#pragma unroll
    for (int mt = 0; mt < 2; mt++) {
        int p = m0 + mt*16 + gid;
#pragma unroll
        for (int nt = 0; nt < 6; nt++) {
            int co = n0 + nt*8 + (tig << 1);
            float* c = acc[mt*6 + nt];
            float bs0 = sbias[co], bs1 = sbias[co+1];
            size_t i00 = obase + (((size_t)co) << 14) + p;
            size_t i10 = obase + (((size_t)co+1) << 14) + p;
            A[i00]     = R[i00]     + 0.5f*c[0] + bs0;
            A[i10]     = R[i10]     + 0.5f*c[1] + bs1;
            A[i00 + 8] = R[i00 + 8] + 0.5f*c[2] + bs0;
            A[i10 + 8] = R[i10 + 8] + 0.5f*c[3] + bs1;
        }
    }
}

// ---------------- GN finalize ------------------------------------------------
__global__ void gn_finalize_k(const float* __restrict__ part, int nch, int sqoff,
                              float* __restrict__ stats)
{
    int bg = threadIdx.x;
    float s = 0, q = 0;
    for (int c = 0; c < nch; c++) {
        s += part[bg*nch + c];
        q += part[sqoff + bg*nch + c];
    }
    float mean = s * (1.f/393216.f);
    float var  = q * (1.f/393216.f) - mean*mean;
    stats[bg*2 + 0] = mean;
    stats[bg*2 + 1] = rsqrtf(var + 1e-5f);
}

// ---------------- time-embedding MLP -----------------------------------------
__global__ void temb_k(const float* __restrict__ te, const float* __restrict__ wt,
                       const float* __restrict__ bt, float* __restrict__ film)
{
    __shared__ float sh[256];
    int b = blockIdx.x, j = blockIdx.y*32 + threadIdx.x;
    for (int i = threadIdx.x; i < 256; i += 32) sh[i] = te[b*256 + i];
    __syncthreads();
    const float* wr = wt + j*256;
    float s = bt[j];
#pragma unroll 4
    for (int k = 0; k < 256; k++) s += sh[k]*wr[k];
    s = s / (1.f + expf(-s));
    film[b*192 + j] = s;
}

// ---------------- apply GN1+SiLU+FiLM, emit GN2 partials ---------------------
__global__ __launch_bounds__(256) void apply1_k(
    const float* __restrict__ x, const float* __restrict__ stats,
    const float* __restrict__ g1, const float* __restrict__ be1,
    const float* __restrict__ film, float* __restrict__ out,
    float* __restrict__ part)
{
    int bg = blockIdx.x, chunk = blockIdx.y;
    int b = bg >> 2, g = bg & 3;
    int tid = threadIdx.x;
    size_t base = (size_t)bg*GN_N + (size_t)chunk*49152;
    float mean = stats[bg*2], rstd = stats[bg*2+1];
    const float4* xp = (const float4*)(x + base);
    float4* op = (float4*)(out + base);

    float sx=0, sy=0, sz=0, sw=0, qx=0, qy=0, qz=0, qw=0;
    for (int i = tid; i < 12288; i += 256) {
        int c = g*24 + chunk*3 + (i >> 12);
        float gam = g1[c]*rstd;
        float bet = be1[c] - mean*gam;
        float shf = 1.f + film[b*192 + c];
        float bia = film[b*192 + 96 + c];
        float4 v = xp[i];
        float t;
        t = v.x*gam + bet; t = t/(1.f+expf(-t)); v.x = t*shf + bia;
        t = v.y*gam + bet; t = t/(1.f+expf(-t)); v.y = t*shf + bia;
        t = v.z*gam + bet; t = t/(1.f+expf(-t)); v.z = t*shf + bia;
        t = v.w*gam + bet; t = t/(1.f+expf(-t)); v.w = t*shf + bia;
        op[i] = v;
        sx += v.x; sy += v.y; sz += v.z; sw += v.w;
        qx += v.x*v.x; qy += v.y*v.y; qz += v.z*v.z; qw += v.w*v.w;
    }
    __shared__ double sh[512];
    sh[tid]       = (double)sx + sy + sz + sw;
    sh[256 + tid] = (double)qx + qy + qz + qw;
    __syncthreads();
    for (int st = 128; st > 0; st >>= 1) {
        if (tid < st) { sh[tid] += sh[tid+st]; sh[256+tid] += sh[256+tid+st]; }
        __syncthreads();
    }
    if (tid == 0) {
        part[bg*8 + chunk]       = (float)sh[0];
        part[512 + bg*8 + chunk] = (float)sh[256];
    }
}

// ---------------- final: SiLU(GN(conv2)) -> d_out ----------------------------
__global__ __launch_bounds__(256) void apply3_k(
    const float* __restrict__ x, const float* __restrict__ stats,
    const float* __restrict__ g2, const float* __restrict__ be2,
    float* __restrict__ out)
{
    int idx4 = blockIdx.x*256 + threadIdx.x;
    if (idx4 >= NPIX/4) return;
    int flat = idx4 << 2;
    int cimg = flat >> 14;
    int b = cimg / 96, c = cimg - 96*b;
    int bg = b*4 + c/24;
    float mean = stats[bg*2], rstd = stats[bg*2+1];
    float gam = g2[c]*rstd;
    float bet = be2[c] - mean*gam;
    float4 v = *(const float4*)&x[flat];
    float t;
    t = v.x*gam + bet; v.x = t/(1.f+expf(-t));
    t = v.y*gam + bet; v.y = t/(1.f+expf(-t));
    t = v.z*gam + bet; v.z = t/(1.f+expf(-t));
    t = v.w*gam + bet; v.w = t/(1.f+expf(-t));
    *(float4*)&out[flat] = v;
}

// ---------------- attention core ---------------------------------------------
__global__ __launch_bounds__(256) void attn_core_k(
    const float* __restrict__ qkv, float* __restrict__ o0, float* __restrict__ o1)
{
    extern __shared__ float sm[];
    float* sq   = sm;
    float* slog = sq + 18432;
    float* spr  = slog + 576;

    int b = blockIdx.y, branch = blockIdx.z;
    int hn = blockIdx.x >> 4, wn = blockIdx.x & 15;
    int sh = branch*4;
    int h0 = hn*8 + sh, w0 = wn*8 + sh;
    int tid = threadIdx.x;

    for (int i = tid; i < 4608; i += 256) {
        int c = i >> 4, lq = i & 15, l = lq << 2;
        int gh = (h0 + (l >> 3)) & 127, gw = (w0 + (l & 7)) & 127;
        *(float4*)&sq[(c << 6) + l] =
            *(const float4*)&qkv[(((size_t)(b*288 + c)) << 14) + (gh << 7) + gw];
    }
    __syncthreads();

    const float scale = 0.40824829046386307f;
    for (int i = tid; i < 576; i += 256) {
        int head = i / 36, r = i - head*36, d = r / 6, e = r - d*6;
        const float* qp = &sq[(head*6 + d) << 6];
        const float* kp = &sq[(96 + head*6 + e) << 6];
        float a = 0.f;
#pragma unroll 8
        for (int l = 0; l < 64; l++) a += qp[l]*kp[l];
        slog[i] = a*scale;
    }
    __syncthreads();

    if (tid < 96) {
        int head = tid / 6, d = tid - head*6, base = head*36 + d*6;
        float m = -1e30f;
#pragma unroll
        for (int e = 0; e < 6; e++) m = fmaxf(m, slog[base+e]);
        float ex[6]; float s = 0.f;
#pragma unroll
        for (int e = 0; e < 6; e++) { ex[e] = expf(slog[base+e] - m); s += ex[e]; }
        float inv = 1.f/s;
#pragma unroll
        for (int e = 0; e < 6; e++) spr[base+e] = ex[e]*inv;
    }
    __syncthreads();

    float* o = branch ? o1 : o0;
    for (int i = tid; i < 1536; i += 256) {
        int ch = i >> 4, lq = i & 15, l = lq << 2;
        int head = ch / 6, d = ch - head*6;
        float4 a = {0.f, 0.f, 0.f, 0.f};
#pragma unroll
        for (int e = 0; e < 6; e++) {
            float p = spr[head*36 + d*6 + e];
            float4 vv = *(const float4*)&sq[((192 + head*6 + e) << 6) + l];
            a.x += p*vv.x; a.y += p*vv.y; a.z += p*vv.z; a.w += p*vv.w;
        }
        int gh = (h0 + (l >> 3)) & 127, gw = (w0 + (l & 7)) & 127;
        *(float4*)&o[(((size_t)(b*96 + ch)) << 14) + (gh << 7) + gw] = a;
    }
}

// ---------------- launch -----------------------------------------------------
extern "C" void kernel_launch(void* const* d_in, const int* in_sizes, int n_in,
                              void* d_out, int out_size)
{
    const float* x      = (const float*)d_in[0];
    const float* t_emb  = (const float*)d_in[1];
    const float* w1     = (const float*)d_in[2];
    const float* b1     = (const float*)d_in[3];
    const float* g1     = (const float*)d_in[4];
    const float* be1    = (const float*)d_in[5];
    const float* wt     = (const float*)d_in[6];
    const float* bt     = (const float*)d_in[7];
    const float* qkv_w  = (const float*)d_in[8];
    const float* qkv_b  = (const float*)d_in[9];
    const float* proj_w = (const float*)d_in[10];
    const float* proj_b = (const float*)d_in[11];
    const float* ga     = (const float*)d_in[12];
    const float* ba     = (const float*)d_in[13];
    const float* w2     = (const float*)d_in[14];
    const float* b2     = (const float*)d_in[15];
    const float* g2     = (const float*)d_in[16];
    const float* be2    = (const float*)d_in[17];
    float* out = (float*)d_out;

    float *buf1, *buf2, *buf3, *buf4, *qkvb, *part0, *part1, *part2, *stats, *film;
    uint32_t *w1hi, *w1lo, *w2hi, *w2lo, *qwhi, *qwlo, *pwhi, *pwlo;
    cudaGetSymbolAddress((void**)&buf1, g_buf1);
    cudaGetSymbolAddress((void**)&buf2, g_buf2);
    cudaGetSymbolAddress((void**)&buf3, g_buf3);
    cudaGetSymbolAddress((void**)&buf4, g_buf4);
    cudaGetSymbolAddress((void**)&qkvb, g_qkv);
    cudaGetSymbolAddress((void**)&part0, g_part0);
    cudaGetSymbolAddress((void**)&part1, g_part1);
    cudaGetSymbolAddress((void**)&part2, g_part2);
    cudaGetSymbolAddress((void**)&stats, g_stats);
    cudaGetSymbolAddress((void**)&film, g_film);
    cudaGetSymbolAddress((void**)&w1hi, g_w1hi);
    cudaGetSymbolAddress((void**)&w1lo, g_w1lo);
    cudaGetSymbolAddress((void**)&w2hi, g_w2hi);
    cudaGetSymbolAddress((void**)&w2lo, g_w2lo);
    cudaGetSymbolAddress((void**)&qwhi, g_qwhi);
    cudaGetSymbolAddress((void**)&qwlo, g_qwlo);
    cudaGetSymbolAddress((void**)&pwhi, g_pwhi);
    cudaGetSymbolAddress((void**)&pwlo, g_pwlo);

    const int ATTN_SMEM = (18432 + 576 + 576) * 4;
    cudaFuncSetAttribute(attn_core_k, cudaFuncAttributeMaxDynamicSharedMemorySize,
                         ATTN_SMEM);
    cudaFuncSetAttribute(conv3x3_mma_k, cudaFuncAttributeMaxDynamicSharedMemorySize,
                         CONV_SMEM);
    cudaFuncSetAttribute(qkv_mma_k, cudaFuncAttributeMaxDynamicSharedMemorySize,
                         QKV_SMEM);
    cudaFuncSetAttribute(proj_mma_k, cudaFuncAttributeMaxDynamicSharedMemorySize,
                         QKV_SMEM);

    dim3 cgrid(128, 16);

    prep_k<<<162, 256>>>(w1, w1hi, w1lo, 41472, 1);
    prep_k<<<162, 256>>>(w2, w2hi, w2lo, 41472, 1);
    prep_k<<<54, 256>>>(qkv_w, qwhi, qwlo, 13824, 0);
    prep_k<<<18, 256>>>(proj_w, pwhi, pwlo, 4608, 0);
    temb_k<<<dim3(16, 6), 32>>>(t_emb, wt, bt, film);
    conv3x3_mma_k<<<cgrid, 512, CONV_SMEM>>>(x, w1hi, w1lo, b1, buf1, part0);
    gn_finalize_k<<<1, 64>>>(part0, 128, 8192, stats + 0*128);
    apply1_k<<<dim3(64, 8), 256>>>(buf1, stats + 0*128, g1, be1, film, buf2, part1);
    gn_finalize_k<<<1, 64>>>(part1, 8, 512, stats + 1*128);
    qkv_mma_k<<<dim3(128, 3, 16), 256, QKV_SMEM>>>(buf2, stats + 1*128, ga, ba,
                                                   qwhi, qwlo, qkv_b, qkvb);
    attn_core_k<<<dim3(256, 16, 2), 256, ATTN_SMEM>>>(qkvb, buf1, buf4);
    proj_mma_k<<<cgrid, 256, QKV_SMEM>>>(buf1, buf4, buf2, pwhi, pwlo,
                                         proj_b, buf3);
    conv3x3_mma_k<<<cgrid, 512, CONV_SMEM>>>(buf3, w2hi, w2lo, b2, buf1, part2);
    gn_finalize_k<<<1, 64>>>(part2, 128, 8192, stats + 2*128);
    apply3_k<<<NPIX/4/256, 256>>>(buf1, stats + 2*128, g2, be2, out);
}